// round 9
// baseline (speedup 1.0000x reference)
#include <cuda_runtime.h>

namespace {
constexpr int kB   = 64;
constexpr int kN   = 883;
constexpr int kT   = 12;
constexpr int kTN  = 16;
constexpr int kTOD = 288;
constexpr int kP   = kB * kN;              // 56512 problems, 4 per warp
constexpr unsigned FM = 0xffffffffu;
} // namespace

__device__ __forceinline__ void process_one(
    int p, size_t tile, int n, int y, int lane, bool lowh,
    const float* __restrict__ enc, const float* __restrict__ dec,
    const float* __restrict__ kb,  const float* __restrict__ vb,
    const float* __restrict__ aw,  const float* __restrict__ ab,
    float* __restrict__ out)
{
    const float* __restrict__ kr = kb + tile + (size_t)y * kT;
    const float* __restrict__ vr = vb + tile + (size_t)y * kT;

    float4 k0 = *(const float4*)(kr);
    float4 k1 = *(const float4*)(kr + 4);
    float4 k2 = *(const float4*)(kr + 8);
    float4 v0 = *(const float4*)(vr);
    float4 v1 = *(const float4*)(vr + 4);
    float4 v2 = *(const float4*)(vr + 8);

    const float* __restrict__ qp = enc + (size_t)p * kT;
    float4 q0 = *(const float4*)(qp);
    float4 q1 = *(const float4*)(qp + 4);
    float4 q2 = *(const float4*)(qp + 8);

    const float* __restrict__ awp = aw + n * (kTN + 1);
    const float aw_y  = __ldg(awp + y);
    const float aw_16 = __ldg(awp + 16);
    const float bias  = __ldg(ab + n);

    // Per-key squared distance.
    float dd = 0.f, df;
    df = q0.x - k0.x; dd = fmaf(df, df, dd);
    df = q0.y - k0.y; dd = fmaf(df, df, dd);
    df = q0.z - k0.z; dd = fmaf(df, df, dd);
    df = q0.w - k0.w; dd = fmaf(df, df, dd);
    df = q1.x - k1.x; dd = fmaf(df, df, dd);
    df = q1.y - k1.y; dd = fmaf(df, df, dd);
    df = q1.z - k1.z; dd = fmaf(df, df, dd);
    df = q1.w - k1.w; dd = fmaf(df, df, dd);
    df = q2.x - k2.x; dd = fmaf(df, df, dd);
    df = q2.y - k2.y; dd = fmaf(df, df, dd);
    df = q2.z - k2.z; dd = fmaf(df, df, dd);
    df = q2.w - k2.w; dd = fmaf(df, df, dd);
    const float dist = sqrtf(dd);

    // ---- wave 1: Sum(d), Sum(d^2), interleaved ----
    float s1 = dist, s2 = dd;
#pragma unroll
    for (int m = 8; m >= 1; m >>= 1) {
        s1 += __shfl_xor_sync(FM, s1, m, 16);
        s2 += __shfl_xor_sync(FM, s2, m, 16);
    }

    // Softmax stats (raw moments, ddof=1; |score| <= 37.5, no max-sub).
    const float mean = s1 * (1.0f / 16.0f);
    const float var  = fmaxf((s2 - s1 * mean) * (1.0f / 15.0f), 0.0f);
    const float istd = __fdividef(10.0f, sqrtf(var) + 1e-6f);
    const float ex   = __expf((mean - dist) * istd);

    const float d16    = 0.34641016151377545871f;
    const float s1b    = s1 + d16;
    const float mean17 = s1b * (1.0f / 17.0f);
    const float var17  = fmaxf((s2 + d16 * d16 - s1b * mean17) * (1.0f / 16.0f), 0.0f);
    const float istd2  = __fdividef(10.0f, sqrtf(var17) + 1e-6f);
    const float e2     = __expf((mean17 - dist) * istd2);
    const float e16    = __expf((mean17 - d16)  * istd2);

    // ---- wave 2: m=8 round on {es, es2, ea, o[0..11]} ----
    float es = ex, es2 = e2, ea = e2 * aw_y;
    float o[12];
    o[0] = ex * v0.x; o[1]  = ex * v0.y; o[2]  = ex * v0.z; o[3]  = ex * v0.w;
    o[4] = ex * v1.x; o[5]  = ex * v1.y; o[6]  = ex * v1.z; o[7]  = ex * v1.w;
    o[8] = ex * v2.x; o[9]  = ex * v2.y; o[10] = ex * v2.z; o[11] = ex * v2.w;

    es  += __shfl_xor_sync(FM, es,  8, 16);
    es2 += __shfl_xor_sync(FM, es2, 8, 16);
    ea  += __shfl_xor_sync(FM, ea,  8, 16);
#pragma unroll
    for (int d = 0; d < 12; ++d)
        o[d] += __shfl_xor_sync(FM, o[d], 8, 16);

    // Fold: low 8-subgroup carries dims 0-5, high subgroup dims 6-11.
    float r[6];
#pragma unroll
    for (int d = 0; d < 6; ++d)
        r[d] = lowh ? o[d] : o[d + 6];

#pragma unroll
    for (int m = 4; m >= 1; m >>= 1) {
        es  += __shfl_xor_sync(FM, es,  m, 16);
        es2 += __shfl_xor_sync(FM, es2, m, 16);
        ea  += __shfl_xor_sync(FM, ea,  m, 16);
#pragma unroll
        for (int d = 0; d < 6; ++d)
            r[d] += __shfl_xor_sync(FM, r[d], m, 16);
    }

    const float inv2 = __fdividef(1.0f, es2 + e16);
    const float w    = (ea + e16 * aw_16) * inv2 + bias;
    const float omw  = (1.0f - w) * __fdividef(1.0f, es);

    const int sub = lane & 7;
    if (sub < 3) {
        const size_t base = (size_t)p * kT + (lowh ? 0 : 6) + 2 * sub;
        float2 d2 = *(const float2*)(dec + base);
        float2 r2 = make_float2(fmaf(omw, r[2 * sub],     w * d2.x),
                                fmaf(omw, r[2 * sub + 1], w * d2.y));
        *(float2*)(out + base) = r2;
    }
}

__global__ void __launch_bounds__(256) mode_att_kernel(
    const float* __restrict__ enc,
    const int*   __restrict__ xm,
    const float* __restrict__ dec,
    const float* __restrict__ kb,
    const float* __restrict__ vb,
    const float* __restrict__ aw,
    const float* __restrict__ ab,
    float*       __restrict__ out)
{
    const int warp = (blockIdx.x * blockDim.x + threadIdx.x) >> 5;
    const int lane = threadIdx.x & 31;
    const int y    = lane & 15;
    const int h    = lane >> 4;
    const bool lowh = (lane & 8) == 0;

    // Iteration 0: p0 = warp*4 + h; iteration 1: p1 = p0 + 2.  (kP % 32 == 0)
    const int p0 = warp * 4 + h;
    const int p1 = p0 + 2;

    const int b0 = p0 / kN, n0 = p0 - b0 * kN;
    const int b1 = p1 / kN, n1 = p1 - b1 * kN;
    const int t0 = __ldg(xm + b0 * 2);
    const int t1 = __ldg(xm + b1 * 2);

    const size_t tile0 = ((size_t)(n0 * kTOD + t0) * kTN) * kT;   // float offset
    const size_t tile1 = ((size_t)(n1 * kTOD + t1) * kTN) * kT;

    // ---- L2 prefetch of iteration-1's K and V tiles (6 lines each, 128B) ----
    if (y < 12) {
        const char* pf = (y < 6)
            ? (const char*)(kb + tile1) + y * 128
            : (const char*)(vb + tile1) + (y - 6) * 128;
        asm volatile("prefetch.global.L2 [%0];" :: "l"(pf));
    }

    process_one(p0, tile0, n0, y, lane, lowh, enc, dec, kb, vb, aw, ab, out);

    // Keep iteration 1's loads from being hoisted into iteration 0
    // (register blowup = R5 failure mode).
    asm volatile("" ::: "memory");

    process_one(p1, tile1, n1, y, lane, lowh, enc, dec, kb, vb, aw, ab, out);
}

extern "C" void kernel_launch(void* const* d_in, const int* in_sizes, int n_in,
                              void* d_out, int out_size) {
    const float* enc = (const float*)d_in[0];
    const int*   xm  = (const int*)  d_in[1];
    const float* dec = (const float*)d_in[2];
    const float* kb  = (const float*)d_in[3];
    const float* vb  = (const float*)d_in[4];
    const float* aw  = (const float*)d_in[5];
    const float* ab  = (const float*)d_in[6];
    float*       out = (float*)d_out;

    const int problems_per_block = 32;            // 8 warps * 4
    const int blocks = kP / problems_per_block;   // 1766 (exact)
    mode_att_kernel<<<blocks, 256>>>(enc, xm, dec, kb, vb, aw, ab, out);
}